// round 8
// baseline (speedup 1.0000x reference)
#include <cuda_runtime.h>
#include <cuda_fp16.h>
#include <mma.h>
#include <stdint.h>

using namespace nvcuda;

#define KK 128
#define BATCH 256
#define DD 1024
#define BK (BATCH*KK)
#define LDA 136           // halves per A/W smem row (272 B)
#define LDS 132           // floats per S smem row

// static scratch (allocation-free rule)
__device__ float  g_buf0[512 * BATCH * KK];
__device__ float  g_buf1[256 * BATCH * KK];
__device__ __half g_wh[1023 * KK * KK];      // softmax(W) fp16

// ---- smem layout (bytes) ----
#define SM_W0   0          // [128][136] fp16 = 34816
#define SM_W1   34816      // [128][136] fp16 = 34816
#define SM_A0   69632      // [32][136] fp16 = 8704
#define SM_A1   78336      // [32][136] fp16 = 8704
#define SM_S0   87040      // [32][132] f32 = 16896 (leaf params alias head)
#define SM_MSUM 103936     // [32] f32
#define SMEM_BYTES (SM_MSUM + 192)   // ~101.7 KB -> 2 blocks/SM

// ---------------- helpers ----------------
static __device__ __forceinline__ uint32_t smem_u32(const void* p) {
    uint32_t a;
    asm("{ .reg .u64 t; cvta.to.shared.u64 t, %1; cvt.u32.u64 %0, t; }" : "=r"(a) : "l"(p));
    return a;
}
static __device__ __forceinline__ void cp_async16(uint32_t dst, const void* src) {
    asm volatile("cp.async.cg.shared.global [%0], [%1], 16;" :: "r"(dst), "l"(src));
}
static __device__ __forceinline__ void cp_commit() {
    asm volatile("cp.async.commit_group;" ::: "memory");
}
template<int N> static __device__ __forceinline__ void cp_wait() {
    asm volatile("cp.async.wait_group %0;" :: "n"(N) : "memory");
}
static __device__ __forceinline__ float warp_max(float m) {
    #pragma unroll
    for (int o = 16; o; o >>= 1) m = fmaxf(m, __shfl_xor_sync(0xffffffffu, m, o));
    return m;
}
static __device__ __forceinline__ float max4(float4 v) {
    return fmaxf(fmaxf(v.x, v.y), fmaxf(v.z, v.w));
}

// ---------------- K0: softmax(W) -> fp16, all nodes ----------------
__global__ void __launch_bounds__(256) softmax_w_kernel(const float* __restrict__ w) {
    const int node = blockIdx.x;
    const int wid = threadIdx.x >> 5, lane = threadIdx.x & 31;
    const float* wn = w + (size_t)node * (KK * KK);
    __half* out = g_wh + (size_t)node * (KK * KK);
    for (int i = wid; i < KK; i += 8) {
        float4 v = ((const float4*)(wn + i * KK))[lane];
        float m = warp_max(max4(v));
        float e0 = __expf(v.x - m), e1 = __expf(v.y - m);
        float e2 = __expf(v.z - m), e3 = __expf(v.w - m);
        float s = e0 + e1 + e2 + e3;
        #pragma unroll
        for (int o = 16; o; o >>= 1) s += __shfl_xor_sync(0xffffffffu, s, o);
        float inv = 1.0f / s;
        __half2 h0 = __floats2half2_rn(e0 * inv, e1 * inv);
        __half2 h1 = __floats2half2_rn(e2 * inv, e3 * inv);
        uint2 pk; pk.x = *(uint32_t*)&h0; pk.y = *(uint32_t*)&h1;
        *(uint2*)&out[i * KK + 4 * lane] = pk;
    }
}

// in-register 32x128x128 GEMM: acc[m,i] = sum_j A[m,j]*W[i,j]; warp tile 16m x 32n
using AccFrag = wmma::fragment<wmma::accumulator, 16, 16, 16, float>;
static __device__ __forceinline__ void gemm32_acc(const __half* As, const __half* Wh,
                                                  AccFrag acc[2], int wid) {
    const int warp_m = wid & 1, warp_n = wid >> 1;
    const int m_base = warp_m * 16, n_base = warp_n * 32;
    wmma::fill_fragment(acc[0], 0.0f);
    wmma::fill_fragment(acc[1], 0.0f);
    #pragma unroll
    for (int k = 0; k < 8; k++) {
        wmma::fragment<wmma::matrix_a, 16, 16, 16, __half, wmma::row_major> af;
        wmma::load_matrix_sync(af, &As[m_base * LDA + 16 * k], LDA);
        #pragma unroll
        for (int j = 0; j < 2; j++) {
            wmma::fragment<wmma::matrix_b, 16, 16, 16, __half, wmma::col_major> bf;
            wmma::load_matrix_sync(bf, &Wh[(n_base + 16 * j) * LDA + 16 * k], LDA);
            wmma::mma_sync(acc[j], af, bf, acc[j]);
        }
    }
}
static __device__ __forceinline__ void store_acc(AccFrag acc[2], float* Out, int wid) {
    const int warp_m = wid & 1, warp_n = wid >> 1;
    #pragma unroll
    for (int j = 0; j < 2; j++)
        wmma::store_matrix_sync(&Out[(warp_m * 16) * LDS + warp_n * 32 + 16 * j],
                                acc[j], LDS, wmma::mem_row_major);
}
static __device__ __forceinline__ void cp_wtile(uint32_t dst, const __half* wsrc, int tid) {
    const char* ws = (const char*)wsrc;
    #pragma unroll
    for (int c = tid; c < 2048; c += 256)
        cp_async16(dst + (c >> 4) * 272 + (c & 15) * 16, ws + (c >> 4) * 256 + (c & 15) * 16);
    cp_commit();
}

// ---------------- fused level-pair kernel ----------------
// Upper node n from lower children c0=2n, c1=2n+1, inputs = grandchildren 4n..4n+3
// (or leaf Gaussians of vars 4n..4n+3).
// build A0+A1 | GEMM1;GEMM2 back-to-back | product in frags -> S0 |
// renorm -> A0, m' | GEMM3 -> S0 | out = m' + log(S0)
template<bool LEAF>
__global__ void __launch_bounds__(256, 2) pair_kernel(
    int insel, int outsel, int wlo, int wup,
    const float* __restrict__ x, const float* __restrict__ mu,
    const float* __restrict__ ls, float* __restrict__ dout)
{
    extern __shared__ char smem[];
    __half* A0s = (__half*)(smem + SM_A0);
    __half* A1s = (__half*)(smem + SM_A1);
    float* S0  = (float*)(smem + SM_S0);
    float* Pm  = (float*)(smem + SM_S0);     // leaf params alias S0 (dead until product store)
    float* Msum = (float*)(smem + SM_MSUM);
    const uint32_t sb = smem_u32(smem);

    const int tid = threadIdx.x, wid = tid >> 5, lane = tid & 31;
    const int node = blockIdx.y;
    const int b0 = blockIdx.x * 32;

    const float* yin = (insel == 0) ? g_buf0 : g_buf1;
    float* yout = (outsel == 0) ? g_buf0 : ((outsel == 1) ? g_buf1 : dout);

    // prefetch W_c0, W_c1
    cp_wtile(sb + SM_W0, g_wh + (size_t)(wlo + 2 * node) * (KK * KK), tid);
    cp_wtile(sb + SM_W1, g_wh + (size_t)(wlo + 2 * node + 1) * (KK * KK), tid);

    if (LEAF) {
        if (tid < 128) {
            int v0 = 4 * node, v1 = 4 * node + 1, v2 = 4 * node + 2, v3 = 4 * node + 3;
            float l0 = ls[v0 * KK + tid], l1 = ls[v1 * KK + tid];
            float l2 = ls[v2 * KK + tid], l3 = ls[v3 * KK + tid];
            Pm[0 * 128 + tid] = mu[v0 * KK + tid];
            Pm[1 * 128 + tid] = __expf(-l0);
            Pm[2 * 128 + tid] = mu[v1 * KK + tid];
            Pm[3 * 128 + tid] = __expf(-l1);
            Pm[4 * 128 + tid] = -l0 - l1 - 1.8378770664093453f;
            Pm[5 * 128 + tid] = mu[v2 * KK + tid];
            Pm[6 * 128 + tid] = __expf(-l2);
            Pm[7 * 128 + tid] = mu[v3 * KK + tid];
            Pm[8 * 128 + tid] = __expf(-l3);
            Pm[9 * 128 + tid] = -l2 - l3 - 1.8378770664093453f;
        }
        __syncthreads();
    }

    // ---- build BOTH A tiles upfront; Msum[r] = m0+m1 ----
    #pragma unroll
    for (int it = 0; it < 4; it++) {
        const int r = it * 8 + wid;
        float4 v0, v1;
        if (LEAF) {
            float4 xq = *(const float4*)&x[(size_t)(b0 + r) * DD + 4 * node];
            float4 ma0 = *(const float4*)&Pm[0 * 128 + 4 * lane];
            float4 ia0 = *(const float4*)&Pm[1 * 128 + 4 * lane];
            float4 mb0 = *(const float4*)&Pm[2 * 128 + 4 * lane];
            float4 ib0 = *(const float4*)&Pm[3 * 128 + 4 * lane];
            float4 cc0 = *(const float4*)&Pm[4 * 128 + 4 * lane];
            float4 ma1 = *(const float4*)&Pm[5 * 128 + 4 * lane];
            float4 ia1 = *(const float4*)&Pm[6 * 128 + 4 * lane];
            float4 mb1 = *(const float4*)&Pm[7 * 128 + 4 * lane];
            float4 ib1 = *(const float4*)&Pm[8 * 128 + 4 * lane];
            float4 cc1 = *(const float4*)&Pm[9 * 128 + 4 * lane];
            float t, u;
            t = (xq.x - ma0.x) * ia0.x; u = (xq.y - mb0.x) * ib0.x; v0.x = cc0.x - 0.5f * (t*t + u*u);
            t = (xq.x - ma0.y) * ia0.y; u = (xq.y - mb0.y) * ib0.y; v0.y = cc0.y - 0.5f * (t*t + u*u);
            t = (xq.x - ma0.z) * ia0.z; u = (xq.y - mb0.z) * ib0.z; v0.z = cc0.z - 0.5f * (t*t + u*u);
            t = (xq.x - ma0.w) * ia0.w; u = (xq.y - mb0.w) * ib0.w; v0.w = cc0.w - 0.5f * (t*t + u*u);
            t = (xq.z - ma1.x) * ia1.x; u = (xq.w - mb1.x) * ib1.x; v1.x = cc1.x - 0.5f * (t*t + u*u);
            t = (xq.z - ma1.y) * ia1.y; u = (xq.w - mb1.y) * ib1.y; v1.y = cc1.y - 0.5f * (t*t + u*u);
            t = (xq.z - ma1.z) * ia1.z; u = (xq.w - mb1.z) * ib1.z; v1.z = cc1.z - 0.5f * (t*t + u*u);
            t = (xq.z - ma1.w) * ia1.w; u = (xq.w - mb1.w) * ib1.w; v1.w = cc1.w - 0.5f * (t*t + u*u);
        } else {
            const float* yg = yin + ((size_t)(4 * node) * BATCH + b0 + r) * KK;
            float4 a = ((const float4*)yg)[lane];
            float4 b = ((const float4*)(yg + BK))[lane];
            float4 c = ((const float4*)(yg + 2 * BK))[lane];
            float4 d = ((const float4*)(yg + 3 * BK))[lane];
            v0.x = a.x + b.x; v0.y = a.y + b.y; v0.z = a.z + b.z; v0.w = a.w + b.w;
            v1.x = c.x + d.x; v1.y = c.y + d.y; v1.z = c.z + d.z; v1.w = c.w + d.w;
        }
        float m0 = warp_max(max4(v0));
        float m1 = warp_max(max4(v1));
        __half2 h00 = __floats2half2_rn(__expf(v0.x - m0), __expf(v0.y - m0));
        __half2 h01 = __floats2half2_rn(__expf(v0.z - m0), __expf(v0.w - m0));
        __half2 h10 = __floats2half2_rn(__expf(v1.x - m1), __expf(v1.y - m1));
        __half2 h11 = __floats2half2_rn(__expf(v1.z - m1), __expf(v1.w - m1));
        uint2 p0; p0.x = *(uint32_t*)&h00; p0.y = *(uint32_t*)&h01;
        uint2 p1; p1.x = *(uint32_t*)&h10; p1.y = *(uint32_t*)&h11;
        *(uint2*)&A0s[r * LDA + 4 * lane] = p0;
        *(uint2*)&A1s[r * LDA + 4 * lane] = p1;
        if (lane == 0) Msum[r] = m0 + m1;
    }

    AccFrag acc1[2], acc2[2];

    cp_wait<0>();            // W_c0 + W_c1 ready
    __syncthreads();

    // GEMM1 + GEMM2 back-to-back (disjoint read-only inputs, no sync between)
    gemm32_acc(A0s, (const __half*)(smem + SM_W0), acc1, wid);
    gemm32_acc(A1s, (const __half*)(smem + SM_W1), acc2, wid);

    // fragment-space product (identical layouts -> elementwise)
    #pragma unroll
    for (int j = 0; j < 2; j++)
        #pragma unroll
        for (int e = 0; e < acc2[j].num_elements; e++)
            acc2[j].x[e] *= acc1[j].x[e];

    __syncthreads();         // all warps done reading W0/W1/A tiles
    cp_wtile(sb + SM_W0, g_wh + (size_t)(wup + node) * (KK * KK), tid);   // W_up -> W0 slot
    store_acc(acc2, S0, wid);
    __syncthreads();         // S0 visible (also: leaf-param alias dead now)

    // ---- renorm: E' = P/rowmax -> A0, Msum += log(rowmax) ----
    #pragma unroll
    for (int it = 0; it < 4; it++) {
        const int r = it * 8 + wid;
        float4 p = *(const float4*)&S0[r * LDS + 4 * lane];
        float pmax = fmaxf(warp_max(max4(p)), 1e-35f);
        float inv = __fdividef(1.0f, pmax);
        __half2 h0 = __floats2half2_rn(p.x * inv, p.y * inv);
        __half2 h1 = __floats2half2_rn(p.z * inv, p.w * inv);
        uint2 pk; pk.x = *(uint32_t*)&h0; pk.y = *(uint32_t*)&h1;
        *(uint2*)&A0s[r * LDA + 4 * lane] = pk;
        if (lane == 0) Msum[r] += __logf(pmax);
    }

    cp_wait<0>();            // W_up ready
    __syncthreads();
    gemm32_acc(A0s, (const __half*)(smem + SM_W0), acc2, wid);
    store_acc(acc2, S0, wid);
    __syncthreads();

    // ---- epilogue: out = m' + log(s) ----
    {
        const int r = tid >> 3, c0 = (tid & 7) * 16;
        const float mrow = Msum[r];
        float* orow = yout + ((size_t)node * BATCH + b0 + r) * KK + c0;
        #pragma unroll
        for (int c = 0; c < 4; c++) {
            float4 s = *(const float4*)&S0[r * LDS + c0 + 4 * c];
            float4 o;
            o.x = mrow + __logf(s.x); o.y = mrow + __logf(s.y);
            o.z = mrow + __logf(s.z); o.w = mrow + __logf(s.w);
            ((float4*)orow)[c] = o;
        }
    }
}

extern "C" void kernel_launch(void* const* d_in, const int* in_sizes, int n_in,
                              void* d_out, int out_size) {
    const float* x  = (const float*)d_in[0];
    const float* mu = (const float*)d_in[1];
    const float* ls = (const float*)d_in[2];
    const float* w  = (const float*)d_in[3];
    float* out = (float*)d_out;

    cudaFuncSetAttribute(pair_kernel<true>,  cudaFuncAttributeMaxDynamicSharedMemorySize, SMEM_BYTES);
    cudaFuncSetAttribute(pair_kernel<false>, cudaFuncAttributeMaxDynamicSharedMemorySize, SMEM_BYTES);

    softmax_w_kernel<<<1023, 256>>>(w);

    // pairs: (leaf512+256) (128+64) (32+16) (8+4) (2+1)
    pair_kernel<true ><<<dim3(8, 256), 256, SMEM_BYTES>>>(-1, 0, 0,    512,  x, mu, ls, out); // -> buf0 (256 nodes)
    pair_kernel<false><<<dim3(8, 64),  256, SMEM_BYTES>>>( 0, 1, 768,  896,  x, mu, ls, out); // -> buf1 (64)
    pair_kernel<false><<<dim3(8, 16),  256, SMEM_BYTES>>>( 1, 0, 960,  992,  x, mu, ls, out); // -> buf0 (16)
    pair_kernel<false><<<dim3(8, 4),   256, SMEM_BYTES>>>( 0, 1, 1008, 1016, x, mu, ls, out); // -> buf1 (4)
    pair_kernel<false><<<dim3(8, 1),   256, SMEM_BYTES>>>( 1, 2, 1020, 1022, x, mu, ls, out); // -> dout (root)
}